// round 2
// baseline (speedup 1.0000x reference)
#include <cuda_runtime.h>
#include <math.h>
#include <stdint.h>

// ---------------- problem constants ----------------
#define BB    4
#define CCH   7
#define HHH   512
#define WWW   1024
#define HWN   (HHH*WWW)          // 524288
#define NID   7                  // ids 1..7
#define NPAIR (BB*NID)           // 28
#define NBINS 262144             // 2^18 bins over error in [0,2]
#define BINSCALE 131072.0f       // NBINS/2
#define BINW  (2.0f/262144.0f)
#define CHK   4096
#define NCHK  (NBINS/CHK)        // 64

// ---------------- scratch (static __device__, no allocs) ----------------
__device__ float    g_embx[BB*HWN];
__device__ float    g_emby[BB*HWN];
__device__ float    g_seed[BB*HWN];
__device__ unsigned g_hist[(size_t)NPAIR*NBINS*2];   // [pair][bin][{neg,pos}]  ~59MB
__device__ float    g_stats[NPAIR*7];                // cnt, sx, sy, s0, s1, q0, q1
__device__ float    g_der[NPAIR*8];                  // cx, cy, sex, sey, var, present
__device__ unsigned g_ctot[NPAIR*NCHK*2];
__device__ unsigned g_cpre[NPAIR*NCHK*2];
__device__ unsigned g_tot[NPAIR*2];
__device__ float    g_instl[NPAIR];
__device__ float    g_sfg[NPAIR];
__device__ float    g_cls[BB*2];                     // focal sum, valid count
__device__ float    g_sbg[BB];

// ---------------- K0: zero scratch ----------------
__global__ void k0_zero() {
    size_t n4 = ((size_t)NPAIR*NBINS*2) / 4;
    uint4* h4 = reinterpret_cast<uint4*>(g_hist);
    uint4  z  = make_uint4(0u,0u,0u,0u);
    size_t i  = (size_t)blockIdx.x*blockDim.x + threadIdx.x;
    size_t st = (size_t)gridDim.x*blockDim.x;
    for (; i < n4; i += st) h4[i] = z;
    if (blockIdx.x == 0) {
        int t = threadIdx.x;
        for (int j = t; j < NPAIR*7; j += blockDim.x) g_stats[j] = 0.0f;
        if (t < NPAIR) { g_instl[t] = 0.0f; g_sfg[t] = 0.0f; }
        if (t < BB*2)  g_cls[t] = 0.0f;
        if (t < BB)    g_sbg[t] = 0.0f;
    }
}

// ---------------- K1: per-pixel maps + per-(b,id) moments + focal/seed_bg ----------------
__global__ void k1_maps(const float* __restrict__ pred,
                        const int*   __restrict__ inst,
                        const int*   __restrict__ lab) {
    int b = blockIdx.y;
    int p = blockIdx.x*blockDim.x + threadIdx.x;   // 0..HWN-1
    int h = p >> 10;
    int w = p & 1023;

    __shared__ float s_stats[NID*7];
    __shared__ float s_cls[3];                     // focal, count, seed_bg
    if (threadIdx.x < NID*7) s_stats[threadIdx.x] = 0.0f;
    if (threadIdx.x < 3)     s_cls[threadIdx.x]   = 0.0f;
    __syncthreads();

    const float* pb = pred + (size_t)b*CCH*HWN + p;
    float p0 = pb[0];
    float p1 = pb[(size_t)1*HWN];
    float p2 = pb[(size_t)2*HWN];
    float p3 = pb[(size_t)3*HWN];
    float p4 = pb[(size_t)4*HWN];
    float p5 = pb[(size_t)5*HWN];
    float p6 = pb[(size_t)6*HWN];

    float xm = (float)w * (2.0f/2047.0f);
    float ym = (float)h * (1.0f/1023.0f);
    float ex = tanhf(p0) + xm;
    float ey = tanhf(p1) + ym;
    float sd = 1.0f / (1.0f + __expf(-p4));

    size_t gi = (size_t)b*HWN + p;
    g_embx[gi] = ex;
    g_emby[gi] = ey;
    g_seed[gi] = sd;

    int L = lab[gi];
    if (L < 2) {
        float xt = (L == 0) ? p5 : p6;
        float xo = (L == 0) ? p6 : p5;
        float z  = xo - xt;
        float ez = __expf(z);
        float logpt = -log1pf(ez);
        float pt    = 1.0f / (1.0f + ez);
        float om    = 1.0f - pt;
        float focal = -om*om*logpt;
        atomicAdd(&s_cls[0], focal);
        atomicAdd(&s_cls[1], 1.0f);
    }
    if (L == 0) atomicAdd(&s_cls[2], sd*sd);

    int id = inst[gi];
    if (id >= 1) {
        float* s = &s_stats[(id-1)*7];
        atomicAdd(s+0, 1.0f);
        atomicAdd(s+1, xm);
        atomicAdd(s+2, ym);
        atomicAdd(s+3, p2);
        atomicAdd(s+4, p3);
        atomicAdd(s+5, p2*p2);
        atomicAdd(s+6, p3*p3);
    }
    __syncthreads();

    if (threadIdx.x < NID*7) atomicAdd(&g_stats[b*NID*7 + threadIdx.x], s_stats[threadIdx.x]);
    if (threadIdx.x == 0) atomicAdd(&g_cls[b*2+0], s_cls[0]);
    if (threadIdx.x == 1) atomicAdd(&g_cls[b*2+1], s_cls[1]);
    if (threadIdx.x == 2) atomicAdd(&g_sbg[b],     s_cls[2]);
}

// ---------------- K1b: derive per-(b,id) params ----------------
__global__ void k1b_derive() {
    int pr = threadIdx.x;
    if (pr >= NPAIR) return;
    const float* st = &g_stats[pr*7];
    float cnt  = st[0];
    float cntf = fmaxf(cnt, 1.0f);
    float cx = st[1]/cntf, cy = st[2]/cntf;
    float sm0 = st[3]/cntf, sm1 = st[4]/cntf;
    float var = (st[5] - 2.0f*sm0*st[3] + sm0*sm0*cnt
               + st[6] - 2.0f*sm1*st[4] + sm1*sm1*cnt) / (2.0f*cntf);
    float* d = &g_der[pr*8];
    d[0] = cx; d[1] = cy;
    d[2] = expf(10.0f*sm0);
    d[3] = expf(10.0f*sm1);
    d[4] = var;
    d[5] = (cnt > 0.0f) ? 1.0f : 0.0f;
}

// ---------------- K2: dist, error histogram (warp-aggregated), seed_fg ----------------
__global__ void k2_main(const int* __restrict__ inst) {
    int b = blockIdx.y;
    int p = blockIdx.x*blockDim.x + threadIdx.x;
    int tid = threadIdx.x;

    __shared__ float s_sfg[NID];
    if (tid < NID) s_sfg[tid] = 0.0f;
    __syncthreads();

    size_t gi = (size_t)b*HWN + p;
    float ex = g_embx[gi];
    float ey = g_emby[gi];
    float sd = g_seed[gi];
    int   myid = inst[gi];

    float sfg = 0.0f;
    unsigned* hb = g_hist + (size_t)b*NID*NBINS*2;

    #pragma unroll
    for (int i = 0; i < NID; i++) {
        const float* d = &g_der[(b*NID + i)*8];
        float pres = __ldg(&d[5]);
        if (pres == 0.0f) continue;          // uniform across block
        float dx = ex - __ldg(&d[0]);
        float dy = ey - __ldg(&d[1]);
        float q  = dx*dx*__ldg(&d[2]) + dy*dy*__ldg(&d[3]);
        float dist = __expf(-q);
        bool  pos = (myid == i+1);
        float e   = pos ? fmaf(-2.0f, dist, 2.0f) : 2.0f*dist;
        int bin = (int)(e * BINSCALE);
        bin = min(bin, NBINS-1);
        if (pos) { float df = sd - dist; sfg += df*df; }
        unsigned key  = ((unsigned)bin << 1) | (pos ? 1u : 0u);
        unsigned mask = __match_any_sync(0xffffffffu, key);
        int leader = __ffs(mask) - 1;
        if ((tid & 31) == leader)
            atomicAdd(&hb[((size_t)i*NBINS + bin)*2 + (pos ? 1 : 0)],
                      (unsigned)__popc(mask));
    }
    if (myid >= 1) atomicAdd(&s_sfg[myid-1], sfg);
    __syncthreads();
    if (tid < NID) atomicAdd(&g_sfg[b*NID + tid], s_sfg[tid]);
}

// ---------------- K3a: per-chunk totals ----------------
__global__ void k3a_chunks() {
    int pr = blockIdx.y, c = blockIdx.x, tid = threadIdx.x;
    const uint2* h2 = reinterpret_cast<const uint2*>(g_hist) + (size_t)pr*NBINS + (size_t)c*CHK;
    unsigned sN = 0, sP = 0;
    for (int j = tid; j < CHK; j += blockDim.x) {
        uint2 v = h2[j];
        sN += v.x; sP += v.y;
    }
    // warp reduce
    for (int off = 16; off > 0; off >>= 1) {
        sN += __shfl_down_sync(0xffffffffu, sN, off);
        sP += __shfl_down_sync(0xffffffffu, sP, off);
    }
    __shared__ unsigned wN[8], wP[8];
    int lane = tid & 31, warp = tid >> 5;
    if (lane == 0) { wN[warp] = sN; wP[warp] = sP; }
    __syncthreads();
    if (tid == 0) {
        unsigned tN = 0, tP = 0;
        for (int wgo = 0; wgo < 8; wgo++) { tN += wN[wgo]; tP += wP[wgo]; }
        g_ctot[(pr*NCHK + c)*2 + 0] = tN;
        g_ctot[(pr*NCHK + c)*2 + 1] = tP;
    }
}

// ---------------- K3b: descending exclusive scan over chunks ----------------
__global__ void k3b_scan() {
    int pr = threadIdx.x;
    if (pr >= NPAIR) return;
    unsigned runN = 0, runP = 0;
    for (int c = NCHK-1; c >= 0; c--) {     // high bins (high error) first
        g_cpre[(pr*NCHK + c)*2 + 0] = runN;
        g_cpre[(pr*NCHK + c)*2 + 1] = runP;
        runN += g_ctot[(pr*NCHK + c)*2 + 0];
        runP += g_ctot[(pr*NCHK + c)*2 + 1];
    }
    g_tot[pr*2 + 0] = runN;
    g_tot[pr*2 + 1] = runP;
}

// ---------------- K3c: per-bin Lovasz contributions ----------------
__global__ void k3c_lovasz() {
    int pr = blockIdx.y, c = blockIdx.x, tid = threadIdx.x;
    unsigned P = g_tot[pr*2 + 1];
    if (P == 0u) return;                    // id absent -> contribution unused

    const uint2* h2 = reinterpret_cast<const uint2*>(g_hist) + (size_t)pr*NBINS;
    int gtop = (c+1)*CHK - 1;               // descending bin order within chunk

    uint2 loc[16];
    unsigned sN = 0, sP = 0;
    #pragma unroll
    for (int k = 0; k < 16; k++) {
        int g = gtop - (tid*16 + k);
        uint2 v = h2[g];
        loc[k] = v;
        sN += v.x; sP += v.y;
    }

    // block exclusive scan over (sN, sP) in thread order (thread 0 = highest bins)
    int lane = tid & 31, warp = tid >> 5;
    unsigned nI = sN, pI = sP;
    #pragma unroll
    for (int off = 1; off < 32; off <<= 1) {
        unsigned an = __shfl_up_sync(0xffffffffu, nI, off);
        unsigned ap = __shfl_up_sync(0xffffffffu, pI, off);
        if (lane >= off) { nI += an; pI += ap; }
    }
    __shared__ unsigned wN[8], wP[8];
    if (lane == 31) { wN[warp] = nI; wP[warp] = pI; }
    __syncthreads();
    unsigned baseN = 0, baseP = 0;
    for (int wgo = 0; wgo < 8; wgo++)
        if (wgo < warp) { baseN += wN[wgo]; baseP += wP[wgo]; }
    unsigned n0 = g_cpre[(pr*NCHK + c)*2 + 0] + baseN + (nI - sN);
    unsigned p0 = g_cpre[(pr*NCHK + c)*2 + 1] + baseP + (pI - sP);

    float acc = 0.0f;
    #pragma unroll
    for (int k = 0; k < 16; k++) {
        unsigned Ng = loc[k].x, Pg = loc[k].y;
        if (Pg | Ng) {
            int g = gtop - (tid*16 + k);
            float e  = ((float)g + 0.5f) * BINW;
            float d0 = (float)(P + n0);
            if (Pg) acc += e * (float)Pg * __fdividef(1.0f, d0);
            if (Ng) acc += e * (float)(P - p0 - Pg) * (float)Ng
                             * __fdividef(1.0f, d0 * (float)(P + n0 + Ng));
            p0 += Pg; n0 += Ng;
        }
    }

    // block reduce acc
    for (int off = 16; off > 0; off >>= 1)
        acc += __shfl_down_sync(0xffffffffu, acc, off);
    __shared__ float fW[8];
    if (lane == 0) fW[warp] = acc;
    __syncthreads();
    if (tid == 0) {
        float t = 0.0f;
        for (int wgo = 0; wgo < 8; wgo++) t += fW[wgo];
        atomicAdd(&g_instl[pr], t);
    }
}

// ---------------- K4: final combine ----------------
__global__ void k4_final(float* __restrict__ out) {
    if (threadIdx.x != 0) return;
    float totalL = 0.0f, totalC = 0.0f;
    for (int b = 0; b < BB; b++) {
        float presSum = 0.0f, instS = 0.0f, varS = 0.0f, sfgS = 0.0f;
        for (int i = 0; i < NID; i++) {
            int pr = b*NID + i;
            float pres = g_der[pr*8 + 5];
            presSum += pres;
            instS   += g_instl[pr] * pres;
            varS    += g_der[pr*8 + 4] * pres;
            sfgS    += 200.0f * g_sfg[pr] * pres;
        }
        float obj = fmaxf(presSum, 1.0f);
        float seed_loss = (g_sbg[b] + sfgS) * (1.0f/(float)HWN);
        float loss_b = instS/obj + 10.0f*(varS/obj) + seed_loss;
        float cls = g_cls[b*2+0] / fmaxf(g_cls[b*2+1], 1.0f);
        totalL += loss_b;
        totalC += cls;
    }
    out[0] = totalL*(1.0f/BB) + totalC*(1.0f/BB);
}

// ---------------- launcher ----------------
extern "C" void kernel_launch(void* const* d_in, const int* in_sizes, int n_in,
                              void* d_out, int out_size) {
    const float* pred = (const float*)d_in[0];
    const int*   inst = (const int*)d_in[1];
    const int*   lab  = (const int*)d_in[2];
    float* out = (float*)d_out;

    k0_zero<<<2048, 256>>>();
    dim3 gpix(HWN/256, BB);
    k1_maps<<<gpix, 256>>>(pred, inst, lab);
    k1b_derive<<<1, 32>>>();
    k2_main<<<gpix, 256>>>(inst);
    dim3 gchk(NCHK, NPAIR);
    k3a_chunks<<<gchk, 256>>>();
    k3b_scan<<<1, 32>>>();
    k3c_lovasz<<<gchk, 256>>>();
    k4_final<<<1, 32>>>(out);
}

// round 4
// speedup vs baseline: 2.3225x; 2.3225x over previous
#include <cuda_runtime.h>
#include <math.h>
#include <stdint.h>

// ---------------- problem constants ----------------
#define BB    4
#define CCH   7
#define HWN   (512*1024)         // 524288
#define NID   7                  // ids 1..7
#define NPAIR (BB*NID)           // 28
#define NBINS 65536              // 2^16 bins over error in [0,2]
#define BINSCALE 32768.0f
#define BINW  (2.0f/65536.0f)

// ---------------- scratch (static __device__, zero-initialized at load) ----------------
__device__ __align__(16) float    g_emb[BB*HWN*2];                 // interleaved (ex,ey)
__device__ __align__(8)  float    g_seed[BB*HWN];
__device__ __align__(16) unsigned g_hist[(size_t)NPAIR*NBINS*2];   // [pair][bin][{neg,pos}] ~14.7MB, re-zeroed by k3
__device__ float    g_stats[NPAIR*7];                // cnt, sx, sy, s0, s1, q0, q1
__device__ float4   g_par[NPAIR];                    // cx, cy, exp(10 s0m), exp(10 s1m)
__device__ float    g_var[NPAIR];
__device__ float    g_pres[NPAIR];
__device__ float    g_instl[NPAIR];                  // written (not accumulated) by k3
__device__ float    g_sfg[NPAIR];
__device__ float    g_cls[BB*2];
__device__ float    g_sbg[BB];

// ---------------- K0: zero only the small accumulators ----------------
__global__ void k0_small() {
    int t = threadIdx.x;
    if (t < NPAIR*7) g_stats[t] = 0.0f;
    if (t < NPAIR)   g_sfg[t]   = 0.0f;
    if (t < BB*2)    g_cls[t]   = 0.0f;
    if (t < BB)      g_sbg[t]   = 0.0f;
}

__device__ __forceinline__ float fast_tanh(float x) {
    float e2 = __expf(2.0f*x);
    return 1.0f - 2.0f/(e2 + 1.0f);
}

// ---------------- K1: per-pixel maps + per-(b,id) moments + focal/seed_bg ----------------
__global__ void k1_maps(const float* __restrict__ pred,
                        const int*   __restrict__ inst,
                        const int*   __restrict__ lab) {
    int b = blockIdx.y;
    int p = blockIdx.x*blockDim.x + threadIdx.x;   // 0..HWN-1
    int tid = threadIdx.x;
    int lane = tid & 31;
    int h = p >> 10;
    int w = p & 1023;

    __shared__ float s_stats[NID*7];
    __shared__ float s_cls[3];                     // focal, count, seed_bg
    if (tid < NID*7) s_stats[tid] = 0.0f;
    if (tid < 3)     s_cls[tid]   = 0.0f;
    __syncthreads();

    const float* pb = pred + (size_t)b*CCH*HWN + p;
    float p0 = pb[0];
    float p1 = pb[(size_t)1*HWN];
    float p2 = pb[(size_t)2*HWN];
    float p3 = pb[(size_t)3*HWN];
    float p4 = pb[(size_t)4*HWN];
    float p5 = pb[(size_t)5*HWN];
    float p6 = pb[(size_t)6*HWN];

    float xm = (float)w * (2.0f/2047.0f);
    float ym = (float)h * (1.0f/1023.0f);
    float ex = fast_tanh(p0) + xm;
    float ey = fast_tanh(p1) + ym;
    float sd = 1.0f / (1.0f + __expf(-p4));

    size_t gi = (size_t)b*HWN + p;
    ((float2*)g_emb)[gi] = make_float2(ex, ey);
    g_seed[gi] = sd;

    int L = lab[gi];
    float fv = 0.0f;
    if (L < 2) {
        float xt = (L == 0) ? p5 : p6;
        float xo = (L == 0) ? p6 : p5;
        float ez = __expf(xo - xt);
        float pt = 1.0f / (1.0f + ez);
        float om = 1.0f - pt;
        fv = om*om*__logf(1.0f + ez);              // = -(1-pt)^2 * logpt
    }
    float sb = (L == 0) ? sd*sd : 0.0f;

    // warp reduce focal / seed_bg, popc valid count
    #pragma unroll
    for (int off = 16; off > 0; off >>= 1) {
        fv += __shfl_xor_sync(0xffffffffu, fv, off);
        sb += __shfl_xor_sync(0xffffffffu, sb, off);
    }
    int vcnt = __popc(__ballot_sync(0xffffffffu, L < 2));
    if (lane == 0) {
        atomicAdd(&s_cls[0], fv);
        atomicAdd(&s_cls[1], (float)vcnt);
        atomicAdd(&s_cls[2], sb);
    }

    // per-id stats via match_any + integer group reductions (leader-only atomics)
    int id = inst[gi];
    unsigned m = __match_any_sync(0xffffffffu, id);
    int sw = __reduce_add_sync(m, w);
    int sh = __reduce_add_sync(m, h);
    int a2 = __float2int_rn(p2 * 4194304.0f);      // 2^22
    int a3 = __float2int_rn(p3 * 4194304.0f);
    int a4 = __float2int_rn(p2*p2 * 1048576.0f);   // 2^20
    int a5 = __float2int_rn(p3*p3 * 1048576.0f);
    int r2 = __reduce_add_sync(m, a2);
    int r3 = __reduce_add_sync(m, a3);
    int r4 = __reduce_add_sync(m, a4);
    int r5 = __reduce_add_sync(m, a5);
    bool leader = (m & ((1u << lane) - 1u)) == 0u;
    if (id >= 1 && leader) {
        float* s = &s_stats[(id-1)*7];
        atomicAdd(s+0, (float)__popc(m));
        atomicAdd(s+1, (float)sw * (2.0f/2047.0f));
        atomicAdd(s+2, (float)sh * (1.0f/1023.0f));
        atomicAdd(s+3, (float)r2 * (1.0f/4194304.0f));
        atomicAdd(s+4, (float)r3 * (1.0f/4194304.0f));
        atomicAdd(s+5, (float)r4 * (1.0f/1048576.0f));
        atomicAdd(s+6, (float)r5 * (1.0f/1048576.0f));
    }
    __syncthreads();

    if (tid < NID*7) atomicAdd(&g_stats[b*NID*7 + tid], s_stats[tid]);
    if (tid == 0) atomicAdd(&g_cls[b*2+0], s_cls[0]);
    if (tid == 1) atomicAdd(&g_cls[b*2+1], s_cls[1]);
    if (tid == 2) atomicAdd(&g_sbg[b],     s_cls[2]);
}

// ---------------- K1b: derive per-(b,id) params ----------------
__global__ void k1b_derive() {
    int pr = threadIdx.x;
    if (pr >= NPAIR) return;
    const float* st = &g_stats[pr*7];
    float cnt  = st[0];
    float cntf = fmaxf(cnt, 1.0f);
    float cx = st[1]/cntf, cy = st[2]/cntf;
    float sm0 = st[3]/cntf, sm1 = st[4]/cntf;
    float var = (st[5] - 2.0f*sm0*st[3] + sm0*sm0*cnt
               + st[6] - 2.0f*sm1*st[4] + sm1*sm1*cnt) / (2.0f*cntf);
    g_par[pr]  = make_float4(cx, cy, expf(10.0f*sm0), expf(10.0f*sm1));
    g_var[pr]  = var;
    g_pres[pr] = (cnt > 0.0f) ? 1.0f : 0.0f;
}

// ---------------- K2: dist, error histogram (warp-aggregated), seed_fg ----------------
// 2 pixels per thread, params in registers.
__global__ void __launch_bounds__(256) k2_main(const int* __restrict__ inst) {
    int b = blockIdx.y;
    int t = blockIdx.x*blockDim.x + threadIdx.x;   // 0..HWN/2-1
    int tid = threadIdx.x;
    int lane = tid & 31;

    __shared__ float s_sfg[NID];
    if (tid < NID) s_sfg[tid] = 0.0f;
    __syncthreads();

    float4 par[NID];
    #pragma unroll
    for (int i = 0; i < NID; i++) par[i] = __ldg(&g_par[b*NID + i]);

    size_t ti = (size_t)b*(HWN/2) + t;
    float4 e01  = ((const float4*)g_emb)[ti];        // ex0,ey0,ex1,ey1
    float2 sd01 = ((const float2*)g_seed)[ti];
    int2   id01 = ((const int2*)inst)[ti];

    float sfg0 = 0.0f, sfg1 = 0.0f;
    unsigned* hb = g_hist + (size_t)b*NID*NBINS*2;

    #pragma unroll
    for (int i = 0; i < NID; i++) {
        float dx0 = e01.x - par[i].x, dy0 = e01.y - par[i].y;
        float dx1 = e01.z - par[i].x, dy1 = e01.w - par[i].y;
        float q0 = dx0*dx0*par[i].z + dy0*dy0*par[i].w;
        float q1 = dx1*dx1*par[i].z + dy1*dy1*par[i].w;
        float d0 = __expf(-q0);
        float d1 = __expf(-q1);
        bool pos0 = (id01.x == i+1);
        bool pos1 = (id01.y == i+1);
        float e0 = pos0 ? fmaf(-2.0f, d0, 2.0f) : 2.0f*d0;
        float e1 = pos1 ? fmaf(-2.0f, d1, 2.0f) : 2.0f*d1;
        int b0 = min((int)(e0 * BINSCALE), NBINS-1);
        int b1 = min((int)(e1 * BINSCALE), NBINS-1);
        if (pos0) { float df = sd01.x - d0; sfg0 += df*df; }
        if (pos1) { float df = sd01.y - d1; sfg1 += df*df; }

        unsigned key0 = ((unsigned)b0 << 1) | (pos0 ? 1u : 0u);
        unsigned m0 = __match_any_sync(0xffffffffu, key0);
        if ((m0 & ((1u << lane) - 1u)) == 0u)
            atomicAdd(&hb[((size_t)i*NBINS + b0)*2 + (pos0 ? 1 : 0)],
                      (unsigned)__popc(m0));

        unsigned key1 = ((unsigned)b1 << 1) | (pos1 ? 1u : 0u);
        unsigned m1 = __match_any_sync(0xffffffffu, key1);
        if ((m1 & ((1u << lane) - 1u)) == 0u)
            atomicAdd(&hb[((size_t)i*NBINS + b1)*2 + (pos1 ? 1 : 0)],
                      (unsigned)__popc(m1));
    }
    if (id01.x >= 1) atomicAdd(&s_sfg[id01.x-1], sfg0);
    if (id01.y >= 1) atomicAdd(&s_sfg[id01.y-1], sfg1);
    __syncthreads();
    if (tid < NID) atomicAdd(&g_sfg[b*NID + tid], s_sfg[tid]);
}

// ---------------- K3: merged totals + descending scan + Lovasz; zeroes hist ----------------
// One block per pair (28 blocks x 1024 threads). Pass 1: total P. Pass 2 (L2-hot):
// descending chunk scan, 2 bins per thread per chunk, closed-form contributions,
// zero-store the histogram on the way (replay determinism).
__global__ void __launch_bounds__(1024) k3_lovasz() {
    int pr = blockIdx.x;
    int tid = threadIdx.x;
    int lane = tid & 31, wid = tid >> 5;

    uint4* h4 = (uint4*)(g_hist + (size_t)pr*NBINS*2);   // one uint4 = 2 bins

    // pass 1: total positives
    unsigned sP = 0;
    for (int j = tid; j < NBINS/2; j += 1024) {
        uint4 v = h4[j];
        sP += v.y + v.w;
    }
    #pragma unroll
    for (int off = 16; off > 0; off >>= 1)
        sP += __shfl_down_sync(0xffffffffu, sP, off);
    __shared__ unsigned s_w[32];
    if (lane == 0) s_w[wid] = sP;
    __syncthreads();
    __shared__ unsigned s_P;
    if (tid == 0) {
        unsigned tot = 0;
        #pragma unroll
        for (int k = 0; k < 32; k++) tot += s_w[k];
        s_P = tot;
    }
    __syncthreads();
    unsigned P = s_P;

    __shared__ unsigned s_scanN[32], s_scanP[32];
    __shared__ unsigned s_run[2];
    if (tid == 0) { s_run[0] = 0u; s_run[1] = 0u; }
    __syncthreads();

    float acc = 0.0f;
    for (int c = 0; c < 32; c++) {
        int hi = NBINS-1 - (c*2048 + 2*tid);     // thread order = descending bins
        int lo = hi - 1;
        int vidx = lo >> 1;
        uint4 v = h4[vidx];                      // loN, loP, hiN, hiP
        h4[vidx] = make_uint4(0u,0u,0u,0u);      // re-zero for next graph replay

        unsigned tN = v.x + v.z, tP = v.y + v.w;
        unsigned iN = tN, iP = tP;
        #pragma unroll
        for (int off = 1; off < 32; off <<= 1) {
            unsigned an = __shfl_up_sync(0xffffffffu, iN, off);
            unsigned ap = __shfl_up_sync(0xffffffffu, iP, off);
            if (lane >= off) { iN += an; iP += ap; }
        }
        if (lane == 31) { s_scanN[wid] = iN; s_scanP[wid] = iP; }
        __syncthreads();
        unsigned bN = s_run[0], bP = s_run[1];
        for (int k = 0; k < wid; k++) { bN += s_scanN[k]; bP += s_scanP[k]; }
        unsigned n0 = bN + iN - tN;              // negs with strictly higher error
        unsigned p0 = bP + iP - tP;              // poss with strictly higher error

        if (P) {
            // hi bin first (higher error), positives before negatives within bin
            unsigned Ng = v.z, Pg = v.w;
            if (Ng | Pg) {
                float e  = ((float)hi + 0.5f) * BINW;
                float d0 = (float)(P + n0);
                if (Pg) acc += e * (float)Pg * __fdividef(1.0f, d0);
                if (Ng) acc += e * (float)(P - p0 - Pg) * (float)Ng
                                 * __fdividef(1.0f, d0 * (d0 + (float)Ng));
                n0 += Ng; p0 += Pg;
            }
            Ng = v.x; Pg = v.y;
            if (Ng | Pg) {
                float e  = ((float)lo + 0.5f) * BINW;
                float d0 = (float)(P + n0);
                if (Pg) acc += e * (float)Pg * __fdividef(1.0f, d0);
                if (Ng) acc += e * (float)(P - p0 - Pg) * (float)Ng
                                 * __fdividef(1.0f, d0 * (d0 + (float)Ng));
            }
        }
        __syncthreads();
        if (tid == 1023) { s_run[0] = bN + iN; s_run[1] = bP + iP; }
        __syncthreads();
    }

    // block reduce acc
    #pragma unroll
    for (int off = 16; off > 0; off >>= 1)
        acc += __shfl_down_sync(0xffffffffu, acc, off);
    __shared__ float s_f[32];
    if (lane == 0) s_f[wid] = acc;
    __syncthreads();
    if (tid == 0) {
        float tot = 0.0f;
        #pragma unroll
        for (int k = 0; k < 32; k++) tot += s_f[k];
        g_instl[pr] = tot;
    }
}

// ---------------- K4: final combine (one warp, parallel loads) ----------------
__global__ void k4_final(float* __restrict__ out) {
    int tid = threadIdx.x;   // 32 threads
    __shared__ float sb_pres[BB], sb_inst[BB], sb_var[BB], sb_sfg[BB];
    if (tid < BB) { sb_pres[tid]=0.f; sb_inst[tid]=0.f; sb_var[tid]=0.f; sb_sfg[tid]=0.f; }
    __syncthreads();
    if (tid < NPAIR) {
        float pres = g_pres[tid];
        float il = g_instl[tid]*pres;
        float vv = g_var[tid]*pres;
        float sf = 200.0f*g_sfg[tid]*pres;
        int bb = tid / NID;
        atomicAdd(&sb_pres[bb], pres);
        atomicAdd(&sb_inst[bb], il);
        atomicAdd(&sb_var[bb],  vv);
        atomicAdd(&sb_sfg[bb],  sf);
    }
    __syncthreads();
    float tot = 0.0f;
    if (tid < BB) {
        float obj  = fmaxf(sb_pres[tid], 1.0f);
        float seed = (g_sbg[tid] + sb_sfg[tid]) * (1.0f/(float)HWN);
        float lb   = sb_inst[tid]/obj + 10.0f*(sb_var[tid]/obj) + seed;
        float cls  = g_cls[tid*2+0] / fmaxf(g_cls[tid*2+1], 1.0f);
        tot = lb + cls;
    }
    tot += __shfl_xor_sync(0xffffffffu, tot, 1);
    tot += __shfl_xor_sync(0xffffffffu, tot, 2);
    if (tid == 0) out[0] = tot * 0.25f;
}

// ---------------- launcher ----------------
extern "C" void kernel_launch(void* const* d_in, const int* in_sizes, int n_in,
                              void* d_out, int out_size) {
    const float* pred = (const float*)d_in[0];
    const int*   inst = (const int*)d_in[1];
    const int*   lab  = (const int*)d_in[2];
    float* out = (float*)d_out;

    k0_small<<<1, 256>>>();
    k1_maps<<<dim3(HWN/256, BB), 256>>>(pred, inst, lab);
    k1b_derive<<<1, 32>>>();
    k2_main<<<dim3(HWN/512, BB), 256>>>(inst);
    k3_lovasz<<<NPAIR, 1024>>>();
    k4_final<<<1, 32>>>(out);
}

// round 6
// speedup vs baseline: 5.1871x; 2.2334x over previous
#include <cuda_runtime.h>
#include <math.h>
#include <stdint.h>

// ---------------- problem constants ----------------
#define BB    4
#define CCH   7
#define HWN   (512*1024)         // 524288
#define NID   7                  // ids 1..7
#define NPAIR (BB*NID)           // 28
#define NBINS 8192               // bins over error in [0,2]
#define BINW  (2.0f/8192.0f)
#define NSLICE 16
#define PXS   (HWN/NSLICE)       // 32768 pixels per k2 block

// ---------------- scratch (static __device__, zero-initialized at load) ----------------
__device__ __align__(16) float    g_emb[BB*HWN*2];                 // interleaved (ex,ey)
__device__ __align__(8)  float    g_seed[BB*HWN];
__device__ __align__(16) unsigned g_part[(size_t)NPAIR*NSLICE*NBINS]; // packed u16 neg|pos, 14.7MB, fully overwritten by k2
__device__ float    g_stats[NPAIR*7];                // cnt, sx, sy, s0, s1, q0, q1
__device__ float4   g_par[NPAIR];                    // cx, cy, -log2e*exp(10 s0m), -log2e*exp(10 s1m)
__device__ float    g_var[NPAIR];
__device__ float    g_pres[NPAIR];
__device__ float    g_instl[NPAIR];                  // written by k3
__device__ float    g_sfg[NPAIR];
__device__ float    g_cls[BB*2];
__device__ float    g_sbg[BB];

// ---------------- K0: zero only the small accumulators ----------------
__global__ void k0_small() {
    int t = threadIdx.x;
    if (t < NPAIR*7) g_stats[t] = 0.0f;
    if (t < NPAIR)   g_sfg[t]   = 0.0f;
    if (t < BB*2)    g_cls[t]   = 0.0f;
    if (t < BB)      g_sbg[t]   = 0.0f;
}

__device__ __forceinline__ float fast_tanh(float x) {
    float e2 = __expf(2.0f*x);
    return 1.0f - 2.0f/(e2 + 1.0f);
}

// ---------------- K1: per-pixel maps + per-(b,id) moments + focal/seed_bg ----------------
__global__ void k1_maps(const float* __restrict__ pred,
                        const int*   __restrict__ inst,
                        const int*   __restrict__ lab) {
    int b = blockIdx.y;
    int p = blockIdx.x*blockDim.x + threadIdx.x;   // 0..HWN-1
    int tid = threadIdx.x;
    int lane = tid & 31;
    int h = p >> 10;
    int w = p & 1023;

    __shared__ float s_stats[NID*7];
    __shared__ float s_cls[3];                     // focal, count, seed_bg
    if (tid < NID*7) s_stats[tid] = 0.0f;
    if (tid < 3)     s_cls[tid]   = 0.0f;
    __syncthreads();

    const float* pb = pred + (size_t)b*CCH*HWN + p;
    float p0 = pb[0];
    float p1 = pb[(size_t)1*HWN];
    float p2 = pb[(size_t)2*HWN];
    float p3 = pb[(size_t)3*HWN];
    float p4 = pb[(size_t)4*HWN];
    float p5 = pb[(size_t)5*HWN];
    float p6 = pb[(size_t)6*HWN];

    float xm = (float)w * (2.0f/2047.0f);
    float ym = (float)h * (1.0f/1023.0f);
    float ex = fast_tanh(p0) + xm;
    float ey = fast_tanh(p1) + ym;
    float sd = 1.0f / (1.0f + __expf(-p4));

    size_t gi = (size_t)b*HWN + p;
    ((float2*)g_emb)[gi] = make_float2(ex, ey);
    g_seed[gi] = sd;

    int L = lab[gi];
    float fv = 0.0f;
    if (L < 2) {
        float xt = (L == 0) ? p5 : p6;
        float xo = (L == 0) ? p6 : p5;
        float ez = __expf(xo - xt);
        float pt = 1.0f / (1.0f + ez);
        float om = 1.0f - pt;
        fv = om*om*__logf(1.0f + ez);              // = -(1-pt)^2 * logpt
    }
    float sb = (L == 0) ? sd*sd : 0.0f;

    #pragma unroll
    for (int off = 16; off > 0; off >>= 1) {
        fv += __shfl_xor_sync(0xffffffffu, fv, off);
        sb += __shfl_xor_sync(0xffffffffu, sb, off);
    }
    int vcnt = __popc(__ballot_sync(0xffffffffu, L < 2));
    if (lane == 0) {
        atomicAdd(&s_cls[0], fv);
        atomicAdd(&s_cls[1], (float)vcnt);
        atomicAdd(&s_cls[2], sb);
    }

    // per-id stats via match_any + integer group reductions (leader-only atomics)
    int id = inst[gi];
    unsigned m = __match_any_sync(0xffffffffu, id);
    int sw = __reduce_add_sync(m, w);
    int sh = __reduce_add_sync(m, h);
    int a2 = __float2int_rn(p2 * 4194304.0f);      // 2^22
    int a3 = __float2int_rn(p3 * 4194304.0f);
    int a4 = __float2int_rn(p2*p2 * 1048576.0f);   // 2^20
    int a5 = __float2int_rn(p3*p3 * 1048576.0f);
    int r2 = __reduce_add_sync(m, a2);
    int r3 = __reduce_add_sync(m, a3);
    int r4 = __reduce_add_sync(m, a4);
    int r5 = __reduce_add_sync(m, a5);
    bool leader = (m & ((1u << lane) - 1u)) == 0u;
    if (id >= 1 && leader) {
        float* s = &s_stats[(id-1)*7];
        atomicAdd(s+0, (float)__popc(m));
        atomicAdd(s+1, (float)sw * (2.0f/2047.0f));
        atomicAdd(s+2, (float)sh * (1.0f/1023.0f));
        atomicAdd(s+3, (float)r2 * (1.0f/4194304.0f));
        atomicAdd(s+4, (float)r3 * (1.0f/4194304.0f));
        atomicAdd(s+5, (float)r4 * (1.0f/1048576.0f));
        atomicAdd(s+6, (float)r5 * (1.0f/1048576.0f));
    }
    __syncthreads();

    if (tid < NID*7) atomicAdd(&g_stats[b*NID*7 + tid], s_stats[tid]);
    if (tid == 0) atomicAdd(&g_cls[b*2+0], s_cls[0]);
    if (tid == 1) atomicAdd(&g_cls[b*2+1], s_cls[1]);
    if (tid == 2) atomicAdd(&g_sbg[b],     s_cls[2]);
}

// ---------------- K1b: derive per-(b,id) params (scales pre-folded for EX2 binning) ----------------
__global__ void k1b_derive() {
    int pr = threadIdx.x;
    if (pr >= NPAIR) return;
    const float* st = &g_stats[pr*7];
    float cnt  = st[0];
    float cntf = fmaxf(cnt, 1.0f);
    float cx = st[1]/cntf, cy = st[2]/cntf;
    float sm0 = st[3]/cntf, sm1 = st[4]/cntf;
    float var = (st[5] - 2.0f*sm0*st[3] + sm0*sm0*cnt
               + st[6] - 2.0f*sm1*st[4] + sm1*sm1*cnt) / (2.0f*cntf);
    const float L2E = 1.4426950408889634f;
    g_par[pr]  = make_float4(cx, cy, -L2E*expf(10.0f*sm0), -L2E*expf(10.0f*sm1));
    g_var[pr]  = var;
    g_pres[pr] = (cnt > 0.0f) ? 1.0f : 0.0f;
}

// ---------------- K2: one (b,id) per block, private smem histogram, no global atomics ----------------
// bin_f = 2^(13 - q*log2e) = 8192*exp(-q); neg bin = floor(bin_f), pos bin = floor(8192-bin_f).
// Packed counters: neg in low 16 bits, pos in high 16 bits (<=32768 pixels per block, no overflow).
__global__ void __launch_bounds__(512) k2_main(const int* __restrict__ inst) {
    int blk = blockIdx.x;
    int pr  = blk >> 4;
    int s   = blk & 15;
    int b   = pr / NID;
    int idv = (pr % NID) + 1;
    int tid = threadIdx.x;

    __shared__ unsigned sh[NBINS];                 // 32KB
    #pragma unroll
    for (int j = tid; j < NBINS; j += 512) sh[j] = 0u;
    __syncthreads();

    float4 par = __ldg(&g_par[pr]);
    const float4* emb4 = (const float4*)g_emb;     // 2 pixels per element
    const float2* sd2  = (const float2*)g_seed;
    const int2*   in2  = (const int2*)inst;
    size_t base = (size_t)b*(HWN/2) + (size_t)s*(PXS/2);

    float sfg = 0.0f;
    #pragma unroll 4
    for (int k = 0; k < PXS/2/512; k++) {          // 32 iterations
        size_t ti = base + (size_t)k*512 + tid;
        float4 e01  = emb4[ti];
        float2 sd01 = sd2[ti];
        int2   id01 = in2[ti];
        // pixel 0
        {
            float dx = e01.x - par.x, dy = e01.y - par.y;
            float u = fmaf(dy*dy, par.w, fmaf(dx*dx, par.z, 13.0f));
            float bf; asm("ex2.approx.f32 %0, %1;" : "=f"(bf) : "f"(u));
            bool pos = (id01.x == idv);
            if (pos) { float d = bf*(1.0f/8192.0f); float df = sd01.x - d; sfg += df*df; }
            float fb = pos ? (8192.0f - bf) : bf;
            int bin = min((int)fb, NBINS-1);
            atomicAdd(&sh[bin], pos ? 0x10000u : 1u);
        }
        // pixel 1
        {
            float dx = e01.z - par.x, dy = e01.w - par.y;
            float u = fmaf(dy*dy, par.w, fmaf(dx*dx, par.z, 13.0f));
            float bf; asm("ex2.approx.f32 %0, %1;" : "=f"(bf) : "f"(u));
            bool pos = (id01.y == idv);
            if (pos) { float d = bf*(1.0f/8192.0f); float df = sd01.y - d; sfg += df*df; }
            float fb = pos ? (8192.0f - bf) : bf;
            int bin = min((int)fb, NBINS-1);
            atomicAdd(&sh[bin], pos ? 0x10000u : 1u);
        }
    }
    __syncthreads();

    // stream smem histogram to its private partial slab (plain stores, full overwrite)
    uint4* dst = (uint4*)&g_part[(size_t)blk*NBINS];
    const uint4* src = (const uint4*)sh;
    for (int j = tid; j < NBINS/4; j += 512) dst[j] = src[j];

    // seed_fg block reduction
    #pragma unroll
    for (int off = 16; off > 0; off >>= 1)
        sfg += __shfl_xor_sync(0xffffffffu, sfg, off);
    __shared__ float swr[16];
    if ((tid & 31) == 0) swr[tid >> 5] = sfg;
    __syncthreads();
    if (tid == 0) {
        float t = 0.0f;
        #pragma unroll
        for (int wgo = 0; wgo < 16; wgo++) t += swr[wgo];
        atomicAdd(&g_sfg[pr], t);
    }
}

// ---------------- K3: sum slice partials + descending scan + closed-form Lovasz ----------------
__global__ void __launch_bounds__(1024) k3_lovasz() {
    int pr = blockIdx.x;
    int tid = threadIdx.x;
    int lane = tid & 31, wid = tid >> 5;

    const unsigned* part = &g_part[(size_t)pr*NSLICE*NBINS];

    // pass 1: total positives
    unsigned sP = 0;
    const uint4* p4 = (const uint4*)part;
    for (int j = tid; j < NSLICE*NBINS/4; j += 1024) {
        uint4 v = p4[j];
        sP += (v.x>>16) + (v.y>>16) + (v.z>>16) + (v.w>>16);
    }
    #pragma unroll
    for (int off = 16; off > 0; off >>= 1)
        sP += __shfl_down_sync(0xffffffffu, sP, off);
    __shared__ unsigned s_w[32];
    if (lane == 0) s_w[wid] = sP;
    __syncthreads();
    __shared__ unsigned s_P;
    if (tid == 0) {
        unsigned tot = 0;
        #pragma unroll
        for (int k = 0; k < 32; k++) tot += s_w[k];
        s_P = tot;
    }
    __syncthreads();
    unsigned P = s_P;

    __shared__ unsigned s_scanN[32], s_scanP[32];
    __shared__ unsigned s_run[2];
    if (tid == 0) { s_run[0] = 0u; s_run[1] = 0u; }
    __syncthreads();

    float acc = 0.0f;
    for (int c = 0; c < NBINS/2048; c++) {         // 4 chunks, descending bins
        int lo = NBINS-2 - c*2048 - 2*tid;         // hi = lo+1
        int hi = lo + 1;
        unsigned Nlo=0, Plo=0, Nhi=0, Phi=0;
        #pragma unroll
        for (int s2 = 0; s2 < NSLICE; s2++) {
            uint2 v = *(const uint2*)&part[(size_t)s2*NBINS + lo];
            Nlo += v.x & 0xffffu; Plo += v.x >> 16;
            Nhi += v.y & 0xffffu; Phi += v.y >> 16;
        }
        unsigned tN = Nlo + Nhi, tP = Plo + Phi;
        unsigned iN = tN, iP = tP;
        #pragma unroll
        for (int off = 1; off < 32; off <<= 1) {
            unsigned an = __shfl_up_sync(0xffffffffu, iN, off);
            unsigned ap = __shfl_up_sync(0xffffffffu, iP, off);
            if (lane >= off) { iN += an; iP += ap; }
        }
        if (lane == 31) { s_scanN[wid] = iN; s_scanP[wid] = iP; }
        __syncthreads();
        unsigned bN = s_run[0], bP = s_run[1];
        for (int k = 0; k < wid; k++) { bN += s_scanN[k]; bP += s_scanP[k]; }
        unsigned n0 = bN + iN - tN;                // strictly higher error
        unsigned p0 = bP + iP - tP;

        if (P) {
            unsigned Ng = Nhi, Pg = Phi;           // hi bin first (higher error)
            if (Ng | Pg) {
                float e  = ((float)hi + 0.5f) * BINW;
                float d0 = (float)(P + n0);
                if (Pg) acc += e * (float)Pg * __fdividef(1.0f, d0);
                if (Ng) acc += e * (float)(P - p0 - Pg) * (float)Ng
                                 * __fdividef(1.0f, d0 * (d0 + (float)Ng));
                n0 += Ng; p0 += Pg;
            }
            Ng = Nlo; Pg = Plo;
            if (Ng | Pg) {
                float e  = ((float)lo + 0.5f) * BINW;
                float d0 = (float)(P + n0);
                if (Pg) acc += e * (float)Pg * __fdividef(1.0f, d0);
                if (Ng) acc += e * (float)(P - p0 - Pg) * (float)Ng
                                 * __fdividef(1.0f, d0 * (d0 + (float)Ng));
            }
        }
        __syncthreads();
        if (tid == 1023) { s_run[0] = bN + iN; s_run[1] = bP + iP; }
        __syncthreads();
    }

    #pragma unroll
    for (int off = 16; off > 0; off >>= 1)
        acc += __shfl_down_sync(0xffffffffu, acc, off);
    __shared__ float s_f[32];
    if (lane == 0) s_f[wid] = acc;
    __syncthreads();
    if (tid == 0) {
        float tot = 0.0f;
        #pragma unroll
        for (int k = 0; k < 32; k++) tot += s_f[k];
        g_instl[pr] = tot;
    }
}

// ---------------- K4: final combine (one warp) ----------------
__global__ void k4_final(float* __restrict__ out) {
    int tid = threadIdx.x;   // 32 threads
    __shared__ float sb_pres[BB], sb_inst[BB], sb_var[BB], sb_sfg[BB];
    if (tid < BB) { sb_pres[tid]=0.f; sb_inst[tid]=0.f; sb_var[tid]=0.f; sb_sfg[tid]=0.f; }
    __syncthreads();
    if (tid < NPAIR) {
        float pres = g_pres[tid];
        float il = g_instl[tid]*pres;
        float vv = g_var[tid]*pres;
        float sf = 200.0f*g_sfg[tid]*pres;
        int bb = tid / NID;
        atomicAdd(&sb_pres[bb], pres);
        atomicAdd(&sb_inst[bb], il);
        atomicAdd(&sb_var[bb],  vv);
        atomicAdd(&sb_sfg[bb],  sf);
    }
    __syncthreads();
    float tot = 0.0f;
    if (tid < BB) {
        float obj  = fmaxf(sb_pres[tid], 1.0f);
        float seed = (g_sbg[tid] + sb_sfg[tid]) * (1.0f/(float)HWN);
        float lb   = sb_inst[tid]/obj + 10.0f*(sb_var[tid]/obj) + seed;
        float cls  = g_cls[tid*2+0] / fmaxf(g_cls[tid*2+1], 1.0f);
        tot = lb + cls;
    }
    tot += __shfl_xor_sync(0xffffffffu, tot, 1);
    tot += __shfl_xor_sync(0xffffffffu, tot, 2);
    if (tid == 0) out[0] = tot * 0.25f;
}

// ---------------- launcher ----------------
extern "C" void kernel_launch(void* const* d_in, const int* in_sizes, int n_in,
                              void* d_out, int out_size) {
    const float* pred = (const float*)d_in[0];
    const int*   inst = (const int*)d_in[1];
    const int*   lab  = (const int*)d_in[2];
    float* out = (float*)d_out;

    k0_small<<<1, 256>>>();
    k1_maps<<<dim3(HWN/256, BB), 256>>>(pred, inst, lab);
    k1b_derive<<<1, 32>>>();
    k2_main<<<NPAIR*NSLICE, 512>>>(inst);
    k3_lovasz<<<NPAIR, 1024>>>();
    k4_final<<<1, 32>>>(out);
}

// round 9
// speedup vs baseline: 5.6802x; 1.0951x over previous
#include <cuda_runtime.h>
#include <math.h>
#include <stdint.h>

// ---------------- problem constants ----------------
#define BB    4
#define CCH   7
#define HWN   (512*1024)         // 524288
#define NID   7                  // ids 1..7
#define NPAIR (BB*NID)           // 28
#define NBINS 8192               // bins over error in [0,2]
#define BINW  (2.0f/8192.0f)
#define NSLICE 16
#define PXS   (HWN/NSLICE)       // 32768 pixels per k2 block

// ---------------- scratch (static __device__, zero-initialized at load; every
// run leaves all accumulators re-zeroed, so no zeroing kernel is needed) ------
__device__ __align__(16) float    g_emb[BB*HWN*2];                 // interleaved (ex,ey)
__device__ __align__(8)  float    g_seed[BB*HWN];
__device__ __align__(16) unsigned g_part[(size_t)NPAIR*NSLICE*NBINS]; // packed u16 neg|pos, fully overwritten by k2
__device__ unsigned g_pcnt[NPAIR*NSLICE];            // per-(pair,slice) positive count, overwritten by k2
__device__ float    g_stats[NPAIR*7];                // accumulated by k1, zeroed by k1-last
__device__ float4   g_par[NPAIR];                    // cx, cy, -log2e*exp(10 s0m), -log2e*exp(10 s1m)
__device__ float    g_var[NPAIR];
__device__ float    g_pres[NPAIR];
__device__ float    g_instl[NPAIR];                  // written by k3
__device__ float    g_sfg[NPAIR];                    // accumulated by k2, zeroed by k3-last
__device__ float    g_cls[BB*2];                     // accumulated by k1, zeroed by k3-last
__device__ float    g_sbg[BB];                       // accumulated by k1, zeroed by k3-last
__device__ unsigned g_sync1;                         // k1 last-block counter (self-resetting)
__device__ unsigned g_sync3;                         // k3 last-block counter (self-resetting)

__device__ __forceinline__ float tanh_ap(float x) {
    float y; asm("tanh.approx.f32 %0, %1;" : "=f"(y) : "f"(x)); return y;
}

// per-pixel instance stats via match_any + integer group reductions
__device__ __forceinline__ void stats_px(int id, int w, int h, float p2, float p3,
                                         float* s_stats, int lane) {
    unsigned m = __match_any_sync(0xffffffffu, id);
    int wh  = w | (h << 16);
    int swh = __reduce_add_sync(m, wh);
    int a2 = __float2int_rn(p2 * 4194304.0f);      // 2^22
    int a3 = __float2int_rn(p3 * 4194304.0f);
    int a4 = __float2int_rn(p2*p2 * 1048576.0f);   // 2^20
    int a5 = __float2int_rn(p3*p3 * 1048576.0f);
    int r2 = __reduce_add_sync(m, a2);
    int r3 = __reduce_add_sync(m, a3);
    int r4 = __reduce_add_sync(m, a4);
    int r5 = __reduce_add_sync(m, a5);
    bool leader = (m & ((1u << lane) - 1u)) == 0u;
    if (id >= 1 && leader) {
        float* s = &s_stats[(id-1)*7];
        unsigned u = (unsigned)swh;
        atomicAdd(s+0, (float)__popc(m));
        atomicAdd(s+1, (float)(u & 0xffffu) * (2.0f/2047.0f));
        atomicAdd(s+2, (float)(u >> 16)     * (1.0f/1023.0f));
        atomicAdd(s+3, (float)r2 * (1.0f/4194304.0f));
        atomicAdd(s+4, (float)r3 * (1.0f/4194304.0f));
        atomicAdd(s+5, (float)r4 * (1.0f/1048576.0f));
        atomicAdd(s+6, (float)r5 * (1.0f/1048576.0f));
    }
}

// ---------------- K1: maps + moments + focal/seed_bg; last block derives params ----
__global__ void __launch_bounds__(256) k1_maps(const float* __restrict__ pred,
                                               const int*   __restrict__ inst,
                                               const int*   __restrict__ lab) {
    int b   = blockIdx.y;
    int t   = blockIdx.x*blockDim.x + threadIdx.x;   // 0..HWN/2-1 (2 px/thread)
    int tid = threadIdx.x;
    int lane = tid & 31;
    int p  = t << 1;
    int h  = p >> 10;
    int w0 = p & 1023;

    __shared__ float s_stats[NID*7];
    __shared__ float s_cls[3];                     // focal, count, seed_bg
    if (tid < NID*7) s_stats[tid] = 0.0f;
    if (tid < 3)     s_cls[tid]   = 0.0f;
    __syncthreads();

    const float* pb = pred + (size_t)b*CCH*HWN;
    float2 c0 = ((const float2*)(pb + (size_t)0*HWN))[t];
    float2 c1 = ((const float2*)(pb + (size_t)1*HWN))[t];
    float2 c2 = ((const float2*)(pb + (size_t)2*HWN))[t];
    float2 c3 = ((const float2*)(pb + (size_t)3*HWN))[t];
    float2 c4 = ((const float2*)(pb + (size_t)4*HWN))[t];
    float2 c5 = ((const float2*)(pb + (size_t)5*HWN))[t];
    float2 c6 = ((const float2*)(pb + (size_t)6*HWN))[t];

    float xm0 = (float)w0 * (2.0f/2047.0f);
    float xm1 = xm0 + (2.0f/2047.0f);
    float ym  = (float)h * (1.0f/1023.0f);
    float ex0 = tanh_ap(c0.x) + xm0, ex1 = tanh_ap(c0.y) + xm1;
    float ey0 = tanh_ap(c1.x) + ym,  ey1 = tanh_ap(c1.y) + ym;
    float sd0 = fmaf(0.5f, tanh_ap(0.5f*c4.x), 0.5f);
    float sd1 = fmaf(0.5f, tanh_ap(0.5f*c4.y), 0.5f);

    size_t ti = (size_t)b*(HWN/2) + t;
    ((float4*)g_emb)[ti]  = make_float4(ex0, ey0, ex1, ey1);
    ((float2*)g_seed)[ti] = make_float2(sd0, sd1);

    int2 L = ((const int2*)lab)[ti];
    float fv = 0.0f, sb = 0.0f;
    if (L.x < 2) {
        float xt = (L.x == 0) ? c5.x : c6.x;
        float xo = (L.x == 0) ? c6.x : c5.x;
        float ez = __expf(xo - xt);
        float om = ez / (1.0f + ez);
        fv += om*om*__logf(1.0f + ez);
    }
    if (L.y < 2) {
        float xt = (L.y == 0) ? c5.y : c6.y;
        float xo = (L.y == 0) ? c6.y : c5.y;
        float ez = __expf(xo - xt);
        float om = ez / (1.0f + ez);
        fv += om*om*__logf(1.0f + ez);
    }
    if (L.x == 0) sb += sd0*sd0;
    if (L.y == 0) sb += sd1*sd1;

    #pragma unroll
    for (int off = 16; off > 0; off >>= 1) {
        fv += __shfl_xor_sync(0xffffffffu, fv, off);
        sb += __shfl_xor_sync(0xffffffffu, sb, off);
    }
    int vcnt = __popc(__ballot_sync(0xffffffffu, L.x < 2))
             + __popc(__ballot_sync(0xffffffffu, L.y < 2));
    if (lane == 0) {
        atomicAdd(&s_cls[0], fv);
        atomicAdd(&s_cls[1], (float)vcnt);
        atomicAdd(&s_cls[2], sb);
    }

    int2 id01 = ((const int2*)inst)[ti];
    stats_px(id01.x, w0,   h, c2.x, c3.x, s_stats, lane);
    stats_px(id01.y, w0+1, h, c2.y, c3.y, s_stats, lane);
    __syncthreads();

    if (tid < NID*7) atomicAdd(&g_stats[b*NID*7 + tid], s_stats[tid]);
    if (tid == 0) atomicAdd(&g_cls[b*2+0], s_cls[0]);
    if (tid == 1) atomicAdd(&g_cls[b*2+1], s_cls[1]);
    if (tid == 2) atomicAdd(&g_sbg[b],     s_cls[2]);
    __syncthreads();

    // ---- last-block: derive per-(b,id) params, then re-zero g_stats + counter ----
    __shared__ bool s_last;
    if (tid == 0) {
        __threadfence();
        unsigned nb = gridDim.x * gridDim.y;
        s_last = (atomicAdd(&g_sync1, 1u) == nb - 1u);
    }
    __syncthreads();
    if (s_last) {
        if (tid < NPAIR) {
            float st0 = __ldcg(&g_stats[tid*7+0]);
            float st1 = __ldcg(&g_stats[tid*7+1]);
            float st2 = __ldcg(&g_stats[tid*7+2]);
            float st3 = __ldcg(&g_stats[tid*7+3]);
            float st4 = __ldcg(&g_stats[tid*7+4]);
            float st5 = __ldcg(&g_stats[tid*7+5]);
            float st6 = __ldcg(&g_stats[tid*7+6]);
            float cnt  = st0;
            float cntf = fmaxf(cnt, 1.0f);
            float cx = st1/cntf, cy = st2/cntf;
            float sm0 = st3/cntf, sm1 = st4/cntf;
            float var = (st5 - 2.0f*sm0*st3 + sm0*sm0*cnt
                       + st6 - 2.0f*sm1*st4 + sm1*sm1*cnt) / (2.0f*cntf);
            const float L2E = 1.4426950408889634f;
            g_par[tid]  = make_float4(cx, cy, -L2E*expf(10.0f*sm0), -L2E*expf(10.0f*sm1));
            g_var[tid]  = var;
            g_pres[tid] = (cnt > 0.0f) ? 1.0f : 0.0f;
            #pragma unroll
            for (int k = 0; k < 7; k++) g_stats[tid*7+k] = 0.0f;   // re-zero for next run
        }
        if (tid == 0) g_sync1 = 0u;
    }
}

// ---------------- K2: one (b,id,slice) per block, private smem histogram ----------------
// bin_f = 2^(13 - q*log2e) = 8192*exp(-q); neg bin = floor(bin_f), pos bin = floor(8192-bin_f).
// Packed counters: neg low 16 bits, pos high 16 bits (<=32768 px/block, no overflow).
__global__ void __launch_bounds__(512) k2_main(const int* __restrict__ inst) {
    int blk = blockIdx.x;
    int pr  = blk >> 4;
    int s   = blk & 15;
    int b   = pr / NID;
    int idv = (pr % NID) + 1;
    int tid = threadIdx.x;

    __shared__ unsigned sh[NBINS];                 // 32KB
    #pragma unroll
    for (int j = tid; j < NBINS; j += 512) sh[j] = 0u;
    __syncthreads();

    float4 par = __ldg(&g_par[pr]);
    const float4* emb4 = (const float4*)g_emb;     // 2 pixels per element
    const float2* sd2  = (const float2*)g_seed;
    const int2*   in2  = (const int2*)inst;
    size_t base = (size_t)b*(HWN/2) + (size_t)s*(PXS/2);

    float sfg = 0.0f;
    int   pcnt = 0;
    #pragma unroll 4
    for (int k = 0; k < PXS/2/512; k++) {          // 32 iterations
        size_t ti = base + (size_t)k*512 + tid;
        float4 e01  = emb4[ti];
        float2 sd01 = sd2[ti];
        int2   id01 = in2[ti];
        // pixel 0
        {
            float dx = e01.x - par.x, dy = e01.y - par.y;
            float u = fmaf(dy*dy, par.w, fmaf(dx*dx, par.z, 13.0f));
            float bf; asm("ex2.approx.f32 %0, %1;" : "=f"(bf) : "f"(u));
            bool pos = (id01.x == idv);
            if (pos) { float d = bf*(1.0f/8192.0f); float df = sd01.x - d; sfg += df*df; pcnt++; }
            float fb = pos ? (8192.0f - bf) : bf;
            int bin = min((int)fb, NBINS-1);
            atomicAdd(&sh[bin], pos ? 0x10000u : 1u);
        }
        // pixel 1
        {
            float dx = e01.z - par.x, dy = e01.w - par.y;
            float u = fmaf(dy*dy, par.w, fmaf(dx*dx, par.z, 13.0f));
            float bf; asm("ex2.approx.f32 %0, %1;" : "=f"(bf) : "f"(u));
            bool pos = (id01.y == idv);
            if (pos) { float d = bf*(1.0f/8192.0f); float df = sd01.y - d; sfg += df*df; pcnt++; }
            float fb = pos ? (8192.0f - bf) : bf;
            int bin = min((int)fb, NBINS-1);
            atomicAdd(&sh[bin], pos ? 0x10000u : 1u);
        }
    }
    __syncthreads();

    // stream smem histogram to its private partial slab (plain stores, full overwrite)
    uint4* dst = (uint4*)&g_part[(size_t)blk*NBINS];
    const uint4* src = (const uint4*)sh;
    for (int j = tid; j < NBINS/4; j += 512) dst[j] = src[j];

    // seed_fg + positive-count block reduction
    #pragma unroll
    for (int off = 16; off > 0; off >>= 1) {
        sfg  += __shfl_xor_sync(0xffffffffu, sfg, off);
        pcnt += __shfl_xor_sync(0xffffffffu, pcnt, off);
    }
    __shared__ float    swr[16];
    __shared__ unsigned swc[16];
    if ((tid & 31) == 0) { swr[tid >> 5] = sfg; swc[tid >> 5] = (unsigned)pcnt; }
    __syncthreads();
    if (tid == 0) {
        float t = 0.0f; unsigned c = 0u;
        #pragma unroll
        for (int wgo = 0; wgo < 16; wgo++) { t += swr[wgo]; c += swc[wgo]; }
        atomicAdd(&g_sfg[pr], t);
        g_pcnt[blk] = c;
    }
}

// ---------------- K3: slice-sum + descending scan + closed-form Lovasz; last block combines ----
__global__ void __launch_bounds__(1024) k3_lovasz(float* __restrict__ out) {
    int pr = blockIdx.x;
    int tid = threadIdx.x;
    int lane = tid & 31, wid = tid >> 5;

    const unsigned* part = &g_part[(size_t)pr*NSLICE*NBINS];

    // total positives from k2's per-slice counts
    __shared__ unsigned s_P;
    if (tid < 32) {
        unsigned v = (tid < NSLICE) ? g_pcnt[pr*NSLICE + tid] : 0u;
        #pragma unroll
        for (int off = 16; off > 0; off >>= 1)
            v += __shfl_xor_sync(0xffffffffu, v, off);
        if (tid == 0) s_P = v;
    }
    __shared__ unsigned s_scanN[32], s_scanP[32];
    __shared__ unsigned s_run[2];
    if (tid == 0) { s_run[0] = 0u; s_run[1] = 0u; }
    __syncthreads();
    unsigned P = s_P;

    float acc = 0.0f;
    for (int c = 0; c < NBINS/2048; c++) {         // 4 chunks, descending bins
        int lo = NBINS-2 - c*2048 - 2*tid;         // hi = lo+1
        int hi = lo + 1;
        unsigned Nlo=0, Plo=0, Nhi=0, Phi=0;
        #pragma unroll
        for (int s2 = 0; s2 < NSLICE; s2++) {
            uint2 v = *(const uint2*)&part[(size_t)s2*NBINS + lo];
            Nlo += v.x & 0xffffu; Plo += v.x >> 16;
            Nhi += v.y & 0xffffu; Phi += v.y >> 16;
        }
        unsigned tN = Nlo + Nhi, tP = Plo + Phi;
        unsigned iN = tN, iP = tP;
        #pragma unroll
        for (int off = 1; off < 32; off <<= 1) {
            unsigned an = __shfl_up_sync(0xffffffffu, iN, off);
            unsigned ap = __shfl_up_sync(0xffffffffu, iP, off);
            if (lane >= off) { iN += an; iP += ap; }
        }
        if (lane == 31) { s_scanN[wid] = iN; s_scanP[wid] = iP; }
        __syncthreads();
        unsigned bN = s_run[0], bP = s_run[1];
        for (int k = 0; k < wid; k++) { bN += s_scanN[k]; bP += s_scanP[k]; }
        unsigned n0 = bN + iN - tN;                // strictly higher error
        unsigned p0 = bP + iP - tP;

        if (P) {
            unsigned Ng = Nhi, Pg = Phi;           // hi bin first (higher error)
            if (Ng | Pg) {
                float e  = ((float)hi + 0.5f) * BINW;
                float d0 = (float)(P + n0);
                if (Pg) acc += e * (float)Pg * __fdividef(1.0f, d0);
                if (Ng) acc += e * (float)(P - p0 - Pg) * (float)Ng
                                 * __fdividef(1.0f, d0 * (d0 + (float)Ng));
                n0 += Ng; p0 += Pg;
            }
            Ng = Nlo; Pg = Plo;
            if (Ng | Pg) {
                float e  = ((float)lo + 0.5f) * BINW;
                float d0 = (float)(P + n0);
                if (Pg) acc += e * (float)Pg * __fdividef(1.0f, d0);
                if (Ng) acc += e * (float)(P - p0 - Pg) * (float)Ng
                                 * __fdividef(1.0f, d0 * (d0 + (float)Ng));
            }
        }
        __syncthreads();
        if (tid == 1023) { s_run[0] = bN + iN; s_run[1] = bP + iP; }
        __syncthreads();
    }

    #pragma unroll
    for (int off = 16; off > 0; off >>= 1)
        acc += __shfl_down_sync(0xffffffffu, acc, off);
    __shared__ float s_f[32];
    if (lane == 0) s_f[wid] = acc;
    __syncthreads();
    if (tid == 0) {
        float tot = 0.0f;
        #pragma unroll
        for (int k = 0; k < 32; k++) tot += s_f[k];
        g_instl[pr] = tot;
    }
    __syncthreads();

    // ---- last-block: final combine (old k4), then re-zero accumulators ----
    __shared__ bool s_last;
    if (tid == 0) {
        __threadfence();
        s_last = (atomicAdd(&g_sync3, 1u) == NPAIR - 1u);
    }
    __syncthreads();
    if (s_last) {
        if (tid < 32) {
            float tot = 0.0f;
            if (tid < BB) {
                float presSum = 0.0f, instS = 0.0f, varS = 0.0f, sfgS = 0.0f;
                #pragma unroll
                for (int i = 0; i < NID; i++) {
                    int q = tid*NID + i;
                    float pres = __ldcg(&g_pres[q]);
                    presSum += pres;
                    instS   += __ldcg(&g_instl[q]) * pres;
                    varS    += __ldcg(&g_var[q])   * pres;
                    sfgS    += 200.0f * __ldcg(&g_sfg[q]) * pres;
                }
                float obj  = fmaxf(presSum, 1.0f);
                float seed = (__ldcg(&g_sbg[tid]) + sfgS) * (1.0f/(float)HWN);
                float lb   = instS/obj + 10.0f*(varS/obj) + seed;
                float cls  = __ldcg(&g_cls[tid*2+0]) / fmaxf(__ldcg(&g_cls[tid*2+1]), 1.0f);
                tot = lb + cls;
            }
            #pragma unroll
            for (int off = 2; off > 0; off >>= 1)
                tot += __shfl_xor_sync(0xffffffffu, tot, off);
            if (tid == 0) out[0] = tot * 0.25f;
        }
        __syncthreads();
        // re-zero accumulators for the next replay
        if (tid < NPAIR) g_sfg[tid] = 0.0f;
        if (tid < BB*2)  g_cls[tid] = 0.0f;
        if (tid < BB)    g_sbg[tid] = 0.0f;
        if (tid == 0)    g_sync3 = 0u;
    }
}

// ---------------- launcher ----------------
extern "C" void kernel_launch(void* const* d_in, const int* in_sizes, int n_in,
                              void* d_out, int out_size) {
    const float* pred = (const float*)d_in[0];
    const int*   inst = (const int*)d_in[1];
    const int*   lab  = (const int*)d_in[2];
    float* out = (float*)d_out;

    k1_maps<<<dim3(HWN/512, BB), 256>>>(pred, inst, lab);
    k2_main<<<NPAIR*NSLICE, 512>>>(inst);
    k3_lovasz<<<NPAIR, 1024>>>(out);
}